// round 14
// baseline (speedup 1.0000x reference)
#include <cuda_runtime.h>
#include <cuda_fp16.h>

#define NN 50000
#define DD 128
#define EE 800000

// Scratch (__device__ globals; no allocations allowed)
__device__ __align__(16) __half g_hh1[NN * DD]; // layer-1 h (fp16)
__device__ __align__(16) __half g_hh2[NN * DD]; // layer-2 h (fp16)
__device__ float  g_z    [NN * DD];             // layer-1 activation (fp32)
__device__ float  g_dinv [NN];
__device__ int    g_cnt  [NN];
__device__ int    g_rowptr[NN + 1];
__device__ int    g_cursor[NN];
__device__ int2   g_sd   [EE];
__device__ int2   g_edge [EE];                  // CSR-ordered (src, dinv[s]*ew bits)
__device__ int    g_bsum [64];
__device__ int    g_boff [64];
__device__ int    g_done;
__device__ int    g_flag;
__device__ int    g_is64;
__device__ float  g_w1hi[DD * DD], g_w1lo[DD * DD];
__device__ float  g_w2hi[DD * DD], g_w2lo[DD * DD];

// ---------------- TF32 helper ----------------
__device__ __forceinline__ unsigned f2tf32(float f) {
    unsigned u;
    asm("cvt.rna.tf32.f32 %0, %1;" : "=r"(u) : "f"(f));
    return u;
}

// ---------------- init ----------------
__global__ void k_init(const int* __restrict__ ei32, int n) {
    int i = blockIdx.x * blockDim.x + threadIdx.x;
    if (i < n) {
        g_dinv[i] = 1.0f;
        g_cnt[i]  = 0;
    }
    if (blockIdx.x == 0 && threadIdx.x == 0) {
        int acc = 0;
#pragma unroll
        for (int k = 0; k < 64; ++k) acc |= ei32[2 * k + 1];
        g_is64 = (acc == 0) ? 1 : 0;
        g_done = 0;
        g_flag = 0;
    }
}

// ---------------- split W1/W2 into tf32 hi/lo ----------------
__global__ void k_splitw(const float* __restrict__ W1,
                         const float* __restrict__ W2) {
    int i = blockIdx.x * blockDim.x + threadIdx.x;
    if (i >= DD * DD) return;
    float w1 = W1[i];
    float h1 = __uint_as_float(f2tf32(w1));
    g_w1hi[i] = h1;
    g_w1lo[i] = __uint_as_float(f2tf32(w1 - h1));
    float w2 = W2[i];
    float h2 = __uint_as_float(f2tf32(w2));
    g_w2hi[i] = h2;
    g_w2lo[i] = __uint_as_float(f2tf32(w2 - h2));
}

// -------- convert + degree + histogram (2 edges/thread, batched loads) --------
__global__ void k_convert(const int* __restrict__ ei32,
                          const float* __restrict__ ew, int E) {
    int t = blockIdx.x * blockDim.x + threadIdx.x;
    int half = (E + 1) >> 1;
    if (t >= half) return;
    int e1 = t, e2 = t + half;
    bool has2 = (e2 < E);
    int is64 = g_is64;

    int s1, d1, s2 = 0, d2 = 0;
    float w1, w2 = 0.f;
    if (is64) {
        s1 = ei32[2 * e1];
        d1 = ei32[2 * (E + e1)];
        if (has2) { s2 = ei32[2 * e2]; d2 = ei32[2 * (E + e2)]; }
    } else {
        s1 = ei32[e1];
        d1 = ei32[E + e1];
        if (has2) { s2 = ei32[e2]; d2 = ei32[E + e2]; }
    }
    w1 = ew[e1];
    if (has2) w2 = ew[e2];

    g_sd[e1] = make_int2(s1, d1);
    if (has2) g_sd[e2] = make_int2(s2, d2);
    atomicAdd(&g_dinv[d1], w1);
    atomicAdd(&g_cnt[d1], 1);
    if (has2) {
        atomicAdd(&g_dinv[d2], w2);
        atomicAdd(&g_cnt[d2], 1);
    }
}

// ------- fused scan: one launch, last-block pattern (+ dinv finalize) -------
__global__ void k_scan_fused(int N) {
    __shared__ int wsum[32];
    int nb   = gridDim.x;
    int b    = blockIdx.x;
    int tid  = threadIdx.x;
    int lane = tid & 31;
    int wid  = tid >> 5;
    int i = b * 1024 + tid;
    int v = (i < N) ? g_cnt[i] : 0;

    int s = v;
#pragma unroll
    for (int o = 1; o < 32; o <<= 1) {
        int t = __shfl_up_sync(0xFFFFFFFFu, s, o);
        if (lane >= o) s += t;
    }
    if (lane == 31) wsum[wid] = s;
    __syncthreads();
    if (wid == 0) {
        int ws = wsum[lane];
#pragma unroll
        for (int o = 1; o < 32; o <<= 1) {
            int t = __shfl_up_sync(0xFFFFFFFFu, ws, o);
            if (lane >= o) ws += t;
        }
        wsum[lane] = ws;
    }
    __syncthreads();

    if (tid == 0) {
        g_bsum[b] = wsum[31];
        __threadfence();
        int t = atomicAdd(&g_done, 1);
        if (t == nb - 1) {
            int run = 0;
            for (int j = 0; j < nb; ++j) {
                int bs = atomicAdd(&g_bsum[j], 0);
                g_boff[j] = run;
                run += bs;
            }
            g_rowptr[N] = run;
            __threadfence();
            atomicExch(&g_flag, 1);
        }
    }
    if (tid == 0) {
        while (atomicAdd(&g_flag, 0) == 0) __nanosleep(64);
    }
    __syncthreads();
    int excl = s - v + ((wid > 0) ? wsum[wid - 1] : 0) + g_boff[b];
    if (i < N) {
        g_rowptr[i] = excl;
        g_cursor[i] = excl;
        float deg = g_dinv[i];
        g_dinv[i] = (deg > 0.0f) ? rsqrtf(deg) : 0.0f;
    }
}

// -------- place edges (4 edges/thread, batched; record = (src, dinv[s]*ew)) --------
__global__ void k_place(const float* __restrict__ ew, int E) {
    int t = blockIdx.x * blockDim.x + threadIdx.x;
    int q = (E + 3) >> 2;
    if (t >= q) return;

    int  eidx[4];
    int2 sd[4];
    float w[4], ds[4];
    int cnt = 0;
#pragma unroll
    for (int u = 0; u < 4; ++u) {
        int e = t + u * q;
        if (e < E) { eidx[cnt] = e; sd[cnt] = g_sd[e]; ++cnt; }
    }
#pragma unroll
    for (int u = 0; u < 4; ++u)
        if (u < cnt) w[u] = ew[eidx[u]];
#pragma unroll
    for (int u = 0; u < 4; ++u)
        if (u < cnt) ds[u] = g_dinv[sd[u].x];
#pragma unroll
    for (int u = 0; u < 4; ++u) {
        if (u < cnt) {
            float wse = ds[u] * w[u];
            int pos = atomicAdd(&g_cursor[sd[u].y], 1);
            g_edge[pos] = make_int2(sd[u].x, __float_as_int(wse));
        }
    }
}

// ---------------- MMA macro ----------------
#define MMA_TF32(d, a0, a1, a2, a3, b0, b1)                                   \
    asm volatile(                                                             \
        "mma.sync.aligned.m16n8k8.row.col.f32.tf32.tf32.f32 "                 \
        "{%0,%1,%2,%3}, {%4,%5,%6,%7}, {%8,%9}, {%0,%1,%2,%3};"               \
        : "+f"(d[0]), "+f"(d[1]), "+f"(d[2]), "+f"(d[3])                      \
        : "r"(a0), "r"(a1), "r"(a2), "r"(a3), "r"(b0), "r"(b1))

// ------- GEMM: hh_dst = fp16(X @ W) -------
__global__ void __launch_bounds__(256)
k_gemm(const float* __restrict__ Xext, int use_gz, int dst2, int tile_base, int N) {
    __shared__ float xs_hi[128][20], xs_lo[128][20];
    __shared__ float ws_hi[16][132], ws_lo[16][132];

    const float* __restrict__ X   = use_gz ? g_z : Xext;
    const float* __restrict__ Whi = use_gz ? g_w2hi : g_w1hi;
    const float* __restrict__ Wlo = use_gz ? g_w2lo : g_w1lo;
    __half* __restrict__ H = dst2 ? g_hh2 : g_hh1;

    int tid  = threadIdx.x;
    int lane = tid & 31;
    int warp = tid >> 5;
    int grp  = lane >> 2;
    int tig  = lane & 3;
    int wm   = warp & 3;
    int wn   = warp >> 2;
    int r0   = (blockIdx.x + tile_base) * 128;

    float acc[2][8][4];
#pragma unroll
    for (int mt = 0; mt < 2; ++mt)
#pragma unroll
        for (int nt = 0; nt < 8; ++nt)
#pragma unroll
            for (int c = 0; c < 4; ++c) acc[mt][nt][c] = 0.0f;

    for (int chunk = 0; chunk < 8; ++chunk) {
        int k0 = chunk * 16;
#pragma unroll
        for (int rep = 0; rep < 2; ++rep) {
            int q   = tid + rep * 256;
            int row = q >> 2;
            int qc  = q & 3;
            float4 v = make_float4(0.f, 0.f, 0.f, 0.f);
            if (r0 + row < N)
                v = *(const float4*)&X[(r0 + row) * DD + k0 + qc * 4];
            float e[4] = {v.x, v.y, v.z, v.w};
#pragma unroll
            for (int j = 0; j < 4; ++j) {
                float hi = __uint_as_float(f2tf32(e[j]));
                xs_hi[row][qc * 4 + j] = hi;
                xs_lo[row][qc * 4 + j] = __uint_as_float(f2tf32(e[j] - hi));
            }
        }
#pragma unroll
        for (int rep = 0; rep < 2; ++rep) {
            int q  = tid + rep * 256;
            int kk = q >> 5;
            int qc = q & 31;
            *(float4*)&ws_hi[kk][qc * 4] = *(const float4*)&Whi[(k0 + kk) * DD + qc * 4];
            *(float4*)&ws_lo[kk][qc * 4] = *(const float4*)&Wlo[(k0 + kk) * DD + qc * 4];
        }
        __syncthreads();

#pragma unroll
        for (int step = 0; step < 2; ++step) {
            int ks = step * 8;
            unsigned a_hi[2][4], a_lo[2][4];
#pragma unroll
            for (int mt = 0; mt < 2; ++mt) {
                int ar = wm * 32 + mt * 16 + grp;
                a_hi[mt][0] = __float_as_uint(xs_hi[ar    ][ks + tig    ]);
                a_hi[mt][1] = __float_as_uint(xs_hi[ar + 8][ks + tig    ]);
                a_hi[mt][2] = __float_as_uint(xs_hi[ar    ][ks + tig + 4]);
                a_hi[mt][3] = __float_as_uint(xs_hi[ar + 8][ks + tig + 4]);
                a_lo[mt][0] = __float_as_uint(xs_lo[ar    ][ks + tig    ]);
                a_lo[mt][1] = __float_as_uint(xs_lo[ar + 8][ks + tig    ]);
                a_lo[mt][2] = __float_as_uint(xs_lo[ar    ][ks + tig + 4]);
                a_lo[mt][3] = __float_as_uint(xs_lo[ar + 8][ks + tig + 4]);
            }
#pragma unroll
            for (int nt = 0; nt < 8; ++nt) {
                int c0 = wn * 64 + nt * 8 + grp;
                unsigned b_hi0 = __float_as_uint(ws_hi[ks + tig    ][c0]);
                unsigned b_hi1 = __float_as_uint(ws_hi[ks + tig + 4][c0]);
                unsigned b_lo0 = __float_as_uint(ws_lo[ks + tig    ][c0]);
                unsigned b_lo1 = __float_as_uint(ws_lo[ks + tig + 4][c0]);
#pragma unroll
                for (int mt = 0; mt < 2; ++mt) {
                    MMA_TF32(acc[mt][nt], a_hi[mt][0], a_hi[mt][1], a_hi[mt][2], a_hi[mt][3], b_hi0, b_hi1);
                    MMA_TF32(acc[mt][nt], a_hi[mt][0], a_hi[mt][1], a_hi[mt][2], a_hi[mt][3], b_lo0, b_lo1);
                    MMA_TF32(acc[mt][nt], a_lo[mt][0], a_lo[mt][1], a_lo[mt][2], a_lo[mt][3], b_hi0, b_hi1);
                }
            }
        }
        __syncthreads();
    }

#pragma unroll
    for (int mt = 0; mt < 2; ++mt) {
#pragma unroll
        for (int nt = 0; nt < 8; ++nt) {
            int row = r0 + wm * 32 + mt * 16 + grp;
            int col = wn * 64 + nt * 8 + 2 * tig;
            if (row < N)
                *(__half2*)&H[row * DD + col] =
                    __floats2half2_rn(acc[mt][nt][0], acc[mt][nt][1]);
            if (row + 8 < N)
                *(__half2*)&H[(row + 8) * DD + col] =
                    __floats2half2_rn(acc[mt][nt][2], acc[mt][nt][3]);
        }
    }
}

// -------- fused aggregate: out = dinv[d]*Σ wse*h[s] + dinv[d]^2*h[d] + b; PReLU --------
__global__ void k_aggregate(const float* __restrict__ b,
                            const float* __restrict__ a,
                            float* __restrict__ Oext, int use_ext, int src2,
                            int node_base, int node_count) {
    int idx = (blockIdx.x * blockDim.x + threadIdx.x) >> 5;
    if (idx >= node_count) return;
    int node = node_base + idx;
    int lane = threadIdx.x & 31;

    const uint2* __restrict__ hh = src2 ? (const uint2*)g_hh2 : (const uint2*)g_hh1;
    float di = g_dinv[node];

    uint2 ps = hh[node * 32 + lane];   // self row
    float2 sa = __half22float2(*(__half2*)&ps.x);
    float2 sb = __half22float2(*(__half2*)&ps.y);

    float4 acc = make_float4(0.f, 0.f, 0.f, 0.f);

    int i   = g_rowptr[node];
    int end = g_rowptr[node + 1];

    while (i + 8 <= end) {
        int2  ee[8];
        uint2 pp[8];
#pragma unroll
        for (int u = 0; u < 8; ++u) ee[u] = g_edge[i + u];
#pragma unroll
        for (int u = 0; u < 8; ++u) pp[u] = hh[ee[u].x * 32 + lane];
#pragma unroll
        for (int u = 0; u < 8; ++u) {
            float w = __int_as_float(ee[u].y);
            float2 fa = __half22float2(*(__half2*)&pp[u].x);
            float2 fb = __half22float2(*(__half2*)&pp[u].y);
            acc.x = fmaf(w, fa.x, acc.x); acc.y = fmaf(w, fa.y, acc.y);
            acc.z = fmaf(w, fb.x, acc.z); acc.w = fmaf(w, fb.y, acc.w);
        }
        i += 8;
    }
    if (i + 4 <= end) {
        int2  ee[4];
        uint2 pp[4];
#pragma unroll
        for (int u = 0; u < 4; ++u) ee[u] = g_edge[i + u];
#pragma unroll
        for (int u = 0; u < 4; ++u) pp[u] = hh[ee[u].x * 32 + lane];
#pragma unroll
        for (int u = 0; u < 4; ++u) {
            float w = __int_as_float(ee[u].y);
            float2 fa = __half22float2(*(__half2*)&pp[u].x);
            float2 fb = __half22float2(*(__half2*)&pp[u].y);
            acc.x = fmaf(w, fa.x, acc.x); acc.y = fmaf(w, fa.y, acc.y);
            acc.z = fmaf(w, fb.x, acc.z); acc.w = fmaf(w, fb.y, acc.w);
        }
        i += 4;
    }
    for (; i < end; ++i) {
        int2 e = g_edge[i];
        float w = __int_as_float(e.y);
        uint2 p = hh[e.x * 32 + lane];
        float2 fa = __half22float2(*(__half2*)&p.x);
        float2 fb = __half22float2(*(__half2*)&p.y);
        acc.x = fmaf(w, fa.x, acc.x); acc.y = fmaf(w, fa.y, acc.y);
        acc.z = fmaf(w, fb.x, acc.z); acc.w = fmaf(w, fb.y, acc.w);
    }

    // v = di*acc + di^2*self + b
    float di2 = di * di;
    float4 bb = ((const float4*)b)[lane];
    float4 v;
    v.x = fmaf(di, acc.x, fmaf(di2, sa.x, bb.x));
    v.y = fmaf(di, acc.y, fmaf(di2, sa.y, bb.y));
    v.z = fmaf(di, acc.z, fmaf(di2, sb.x, bb.z));
    v.w = fmaf(di, acc.w, fmaf(di2, sb.y, bb.w));

    float4 aa = ((const float4*)a)[lane];
    v.x = (v.x > 0.f) ? v.x : aa.x * v.x;
    v.y = (v.y > 0.f) ? v.y : aa.y * v.y;
    v.z = (v.z > 0.f) ? v.z : aa.z * v.z;
    v.w = (v.w > 0.f) ? v.w : aa.w * v.w;

    float4* Z = use_ext ? (float4*)Oext : (float4*)g_z;
    Z[node * 32 + lane] = v;
}

// -------- launch --------
extern "C" void kernel_launch(void* const* d_in, const int* in_sizes, int n_in,
                              void* d_out, int out_size) {
    const float* x  = (const float*)d_in[0];
    const int*   ei = (const int*)d_in[1];
    const float* ew = (const float*)d_in[2];
    const float* W1 = (const float*)d_in[3];
    const float* b1 = (const float*)d_in[4];
    const float* a1 = (const float*)d_in[5];
    const float* W2 = (const float*)d_in[6];
    const float* b2 = (const float*)d_in[7];
    const float* a2 = (const float*)d_in[8];
    float* out = (float*)d_out;

    const int N = in_sizes[0] / DD;   // 50000
    const int E = in_sizes[2];        // 800000
    const int nb = (N + 1023) / 1024; // 49

    cudaStream_t s2;
    cudaEvent_t evFork, evJoin, evA, evB;
    cudaStreamCreateWithFlags(&s2, cudaStreamNonBlocking);
    cudaEventCreateWithFlags(&evFork, cudaEventDisableTiming);
    cudaEventCreateWithFlags(&evJoin, cudaEventDisableTiming);
    cudaEventCreateWithFlags(&evA, cudaEventDisableTiming);
    cudaEventCreateWithFlags(&evB, cudaEventDisableTiming);

    const int gemm_tiles = (N + 127) / 128;       // 391
    const int gt_h0 = gemm_tiles / 2;             // 195
    const int gt_h1 = gemm_tiles - gt_h0;         // 196
    const int n_h0  = gt_h0 * 128;                // 24960
    const int n_h1  = N - n_h0;

    // fork: prep chain on s2
    cudaEventRecord(evFork, 0);
    cudaStreamWaitEvent(s2, evFork, 0);
    k_init      <<<(N + 255) / 256, 256, 0, s2>>>(ei, N);
    k_convert   <<<((E + 1) / 2 + 255) / 256, 256, 0, s2>>>(ei, ew, E);
    k_scan_fused<<<nb, 1024, 0, s2>>>(N);
    k_place     <<<((E + 3) / 4 + 255) / 256, 256, 0, s2>>>(ew, E);
    cudaEventRecord(evJoin, s2);

    // concurrent on s0: W split + full layer-1 GEMM (-> g_hh1)
    k_splitw<<<(DD * DD + 255) / 256, 256>>>(W1, W2);
    k_gemm<<<gemm_tiles, 256>>>(x, 0, 0, 0, N);

    // join; aggregate layer-1 half 0, then overlap GEMM-2 half 0 with agg half 1
    cudaStreamWaitEvent(0, evJoin, 0);
    k_aggregate<<<(n_h0 * 32 + 255) / 256, 256>>>(b1, a1, out, 0, 0, 0, n_h0);
    cudaEventRecord(evA, 0);

    cudaStreamWaitEvent(s2, evA, 0);
    k_gemm<<<gt_h0, 256, 0, s2>>>(nullptr, 1, 1, 0, N);      // rows [0, n_h0) -> g_hh2
    cudaEventRecord(evB, s2);

    k_aggregate<<<(n_h1 * 32 + 255) / 256, 256>>>(b1, a1, out, 0, 0, n_h0, n_h1);
    k_gemm<<<gt_h1, 256>>>(nullptr, 1, 1, gt_h0, N);          // rows [n_h0, N) -> g_hh2

    cudaStreamWaitEvent(0, evB, 0);
    k_aggregate<<<(N * 32 + 255) / 256, 256>>>(b2, a2, out, 1, 1, 0, N);
}

// round 15
// speedup vs baseline: 1.0613x; 1.0613x over previous
#include <cuda_runtime.h>
#include <cuda_fp16.h>

#define NN 50000
#define DD 128
#define EE 800000

// Scratch (__device__ globals; no allocations allowed)
__device__ __align__(16) __half g_hh1[NN * DD]; // layer-1 h (fp16)
__device__ __align__(16) __half g_hh2[NN * DD]; // layer-2 h (fp16)
__device__ float  g_z    [NN * DD];             // layer-1 activation (fp32)
__device__ float  g_dinv [NN];
__device__ int    g_cnt  [NN];
__device__ int    g_rowptr[NN + 1];
__device__ int    g_cursor[NN];
__device__ int2   g_sd   [EE];
__device__ int2   g_edge [EE];                  // CSR-ordered (src, dinv[s]*ew bits)
__device__ int    g_bsum [64];
__device__ int    g_boff [64];
__device__ int    g_done;
__device__ int    g_flag;
__device__ int    g_is64;
__device__ float  g_w1hi[DD * DD], g_w1lo[DD * DD];
__device__ float  g_w2hi[DD * DD], g_w2lo[DD * DD];

// ---------------- TF32 helper ----------------
__device__ __forceinline__ unsigned f2tf32(float f) {
    unsigned u;
    asm("cvt.rna.tf32.f32 %0, %1;" : "=r"(u) : "f"(f));
    return u;
}

// ---------------- init (detect + per-node init + scan flag reset) ----------------
__global__ void k_init(const int* __restrict__ ei32, int n) {
    int i = blockIdx.x * blockDim.x + threadIdx.x;
    if (i < n) {
        g_dinv[i] = 1.0f;
        g_cnt[i]  = 0;
    }
    if (blockIdx.x == 0 && threadIdx.x == 0) {
        int acc = 0;
#pragma unroll
        for (int k = 0; k < 64; ++k) acc |= ei32[2 * k + 1];
        g_is64 = (acc == 0) ? 1 : 0;
        g_done = 0;
        g_flag = 0;
    }
}

// ---------------- split W1/W2 into tf32 hi/lo ----------------
__global__ void k_splitw(const float* __restrict__ W1,
                         const float* __restrict__ W2) {
    int i = blockIdx.x * blockDim.x + threadIdx.x;
    if (i >= DD * DD) return;
    float w1 = W1[i];
    float h1 = __uint_as_float(f2tf32(w1));
    g_w1hi[i] = h1;
    g_w1lo[i] = __uint_as_float(f2tf32(w1 - h1));
    float w2 = W2[i];
    float h2 = __uint_as_float(f2tf32(w2));
    g_w2hi[i] = h2;
    g_w2lo[i] = __uint_as_float(f2tf32(w2 - h2));
}

// ---- convert + degree + histogram (1 edge/thread; int64 read as int2) ----
__global__ void k_convert(const int* __restrict__ ei32,
                          const float* __restrict__ ew, int E) {
    int e = blockIdx.x * blockDim.x + threadIdx.x;
    if (e >= E) return;
    int s, d;
    if (g_is64) {
        const int2* p = (const int2*)ei32;   // int64 little-endian: .x = low word
        s = p[e].x;
        d = p[E + e].x;
    } else {
        s = ei32[e];
        d = ei32[E + e];
    }
    g_sd[e] = make_int2(s, d);
    atomicAdd(&g_dinv[d], ew[e]);
    atomicAdd(&g_cnt[d], 1);
}

// ------- fused scan: one launch, last-block pattern (+ dinv finalize) -------
__global__ void k_scan_fused(int N) {
    __shared__ int wsum[32];
    int nb   = gridDim.x;
    int b    = blockIdx.x;
    int tid  = threadIdx.x;
    int lane = tid & 31;
    int wid  = tid >> 5;
    int i = b * 1024 + tid;
    int v = (i < N) ? g_cnt[i] : 0;

    int s = v;
#pragma unroll
    for (int o = 1; o < 32; o <<= 1) {
        int t = __shfl_up_sync(0xFFFFFFFFu, s, o);
        if (lane >= o) s += t;
    }
    if (lane == 31) wsum[wid] = s;
    __syncthreads();
    if (wid == 0) {
        int ws = wsum[lane];
#pragma unroll
        for (int o = 1; o < 32; o <<= 1) {
            int t = __shfl_up_sync(0xFFFFFFFFu, ws, o);
            if (lane >= o) ws += t;
        }
        wsum[lane] = ws;
    }
    __syncthreads();

    if (tid == 0) {
        g_bsum[b] = wsum[31];
        __threadfence();
        int t = atomicAdd(&g_done, 1);
        if (t == nb - 1) {
            int run = 0;
            for (int j = 0; j < nb; ++j) {
                int bs = atomicAdd(&g_bsum[j], 0);
                g_boff[j] = run;
                run += bs;
            }
            g_rowptr[N] = run;
            __threadfence();
            atomicExch(&g_flag, 1);
        }
    }
    if (tid == 0) {
        while (atomicAdd(&g_flag, 0) == 0) __nanosleep(64);
    }
    __syncthreads();
    int excl = s - v + ((wid > 0) ? wsum[wid - 1] : 0) + g_boff[b];
    if (i < N) {
        g_rowptr[i] = excl;
        g_cursor[i] = excl;
        float deg = g_dinv[i];
        g_dinv[i] = (deg > 0.0f) ? rsqrtf(deg) : 0.0f;
    }
}

// -------- place edges (1 edge/thread; record = (src, dinv[s]*ew)) --------
__global__ void k_place(const float* __restrict__ ew, int E) {
    int e = blockIdx.x * blockDim.x + threadIdx.x;
    if (e >= E) return;
    int2 sd = g_sd[e];
    float wse = g_dinv[sd.x] * ew[e];
    int pos = atomicAdd(&g_cursor[sd.y], 1);
    g_edge[pos] = make_int2(sd.x, __float_as_int(wse));
}

// ---------------- MMA macro ----------------
#define MMA_TF32(d, a0, a1, a2, a3, b0, b1)                                   \
    asm volatile(                                                             \
        "mma.sync.aligned.m16n8k8.row.col.f32.tf32.tf32.f32 "                 \
        "{%0,%1,%2,%3}, {%4,%5,%6,%7}, {%8,%9}, {%0,%1,%2,%3};"               \
        : "+f"(d[0]), "+f"(d[1]), "+f"(d[2]), "+f"(d[3])                      \
        : "r"(a0), "r"(a1), "r"(a2), "r"(a3), "r"(b0), "r"(b1))

// ------- GEMM: hh_dst = fp16(X @ W) -------
__global__ void __launch_bounds__(256)
k_gemm(const float* __restrict__ Xext, int use_gz, int dst2, int N) {
    __shared__ float xs_hi[128][20], xs_lo[128][20];
    __shared__ float ws_hi[16][132], ws_lo[16][132];

    const float* __restrict__ X   = use_gz ? g_z : Xext;
    const float* __restrict__ Whi = use_gz ? g_w2hi : g_w1hi;
    const float* __restrict__ Wlo = use_gz ? g_w2lo : g_w1lo;
    __half* __restrict__ H = dst2 ? g_hh2 : g_hh1;

    int tid  = threadIdx.x;
    int lane = tid & 31;
    int warp = tid >> 5;
    int grp  = lane >> 2;
    int tig  = lane & 3;
    int wm   = warp & 3;
    int wn   = warp >> 2;
    int r0   = blockIdx.x * 128;

    float acc[2][8][4];
#pragma unroll
    for (int mt = 0; mt < 2; ++mt)
#pragma unroll
        for (int nt = 0; nt < 8; ++nt)
#pragma unroll
            for (int c = 0; c < 4; ++c) acc[mt][nt][c] = 0.0f;

    for (int chunk = 0; chunk < 8; ++chunk) {
        int k0 = chunk * 16;
#pragma unroll
        for (int rep = 0; rep < 2; ++rep) {
            int q   = tid + rep * 256;
            int row = q >> 2;
            int qc  = q & 3;
            float4 v = make_float4(0.f, 0.f, 0.f, 0.f);
            if (r0 + row < N)
                v = *(const float4*)&X[(r0 + row) * DD + k0 + qc * 4];
            float e[4] = {v.x, v.y, v.z, v.w};
#pragma unroll
            for (int j = 0; j < 4; ++j) {
                float hi = __uint_as_float(f2tf32(e[j]));
                xs_hi[row][qc * 4 + j] = hi;
                xs_lo[row][qc * 4 + j] = __uint_as_float(f2tf32(e[j] - hi));
            }
        }
#pragma unroll
        for (int rep = 0; rep < 2; ++rep) {
            int q  = tid + rep * 256;
            int kk = q >> 5;
            int qc = q & 31;
            *(float4*)&ws_hi[kk][qc * 4] = *(const float4*)&Whi[(k0 + kk) * DD + qc * 4];
            *(float4*)&ws_lo[kk][qc * 4] = *(const float4*)&Wlo[(k0 + kk) * DD + qc * 4];
        }
        __syncthreads();

#pragma unroll
        for (int step = 0; step < 2; ++step) {
            int ks = step * 8;
            unsigned a_hi[2][4], a_lo[2][4];
#pragma unroll
            for (int mt = 0; mt < 2; ++mt) {
                int ar = wm * 32 + mt * 16 + grp;
                a_hi[mt][0] = __float_as_uint(xs_hi[ar    ][ks + tig    ]);
                a_hi[mt][1] = __float_as_uint(xs_hi[ar + 8][ks + tig    ]);
                a_hi[mt][2] = __float_as_uint(xs_hi[ar    ][ks + tig + 4]);
                a_hi[mt][3] = __float_as_uint(xs_hi[ar + 8][ks + tig + 4]);
                a_lo[mt][0] = __float_as_uint(xs_lo[ar    ][ks + tig    ]);
                a_lo[mt][1] = __float_as_uint(xs_lo[ar + 8][ks + tig    ]);
                a_lo[mt][2] = __float_as_uint(xs_lo[ar    ][ks + tig + 4]);
                a_lo[mt][3] = __float_as_uint(xs_lo[ar + 8][ks + tig + 4]);
            }
#pragma unroll
            for (int nt = 0; nt < 8; ++nt) {
                int c0 = wn * 64 + nt * 8 + grp;
                unsigned b_hi0 = __float_as_uint(ws_hi[ks + tig    ][c0]);
                unsigned b_hi1 = __float_as_uint(ws_hi[ks + tig + 4][c0]);
                unsigned b_lo0 = __float_as_uint(ws_lo[ks + tig    ][c0]);
                unsigned b_lo1 = __float_as_uint(ws_lo[ks + tig + 4][c0]);
#pragma unroll
                for (int mt = 0; mt < 2; ++mt) {
                    MMA_TF32(acc[mt][nt], a_hi[mt][0], a_hi[mt][1], a_hi[mt][2], a_hi[mt][3], b_hi0, b_hi1);
                    MMA_TF32(acc[mt][nt], a_hi[mt][0], a_hi[mt][1], a_hi[mt][2], a_hi[mt][3], b_lo0, b_lo1);
                    MMA_TF32(acc[mt][nt], a_lo[mt][0], a_lo[mt][1], a_lo[mt][2], a_lo[mt][3], b_hi0, b_hi1);
                }
            }
        }
        __syncthreads();
    }

#pragma unroll
    for (int mt = 0; mt < 2; ++mt) {
#pragma unroll
        for (int nt = 0; nt < 8; ++nt) {
            int row = r0 + wm * 32 + mt * 16 + grp;
            int col = wn * 64 + nt * 8 + 2 * tig;
            if (row < N)
                *(__half2*)&H[row * DD + col] =
                    __floats2half2_rn(acc[mt][nt][0], acc[mt][nt][1]);
            if (row + 8 < N)
                *(__half2*)&H[(row + 8) * DD + col] =
                    __floats2half2_rn(acc[mt][nt][2], acc[mt][nt][3]);
        }
    }
}

// -------- fused aggregate: out = dinv[d]*Σ wse*h[s] + dinv[d]^2*h[d] + b; PReLU --------
__global__ void k_aggregate(const float* __restrict__ b,
                            const float* __restrict__ a,
                            float* __restrict__ Oext, int use_ext, int src2, int N) {
    int node = (blockIdx.x * blockDim.x + threadIdx.x) >> 5;
    if (node >= N) return;
    int lane = threadIdx.x & 31;

    const uint2* __restrict__ hh = src2 ? (const uint2*)g_hh2 : (const uint2*)g_hh1;
    float di = g_dinv[node];

    uint2 ps = hh[node * 32 + lane];   // self row
    float2 sa = __half22float2(*(__half2*)&ps.x);
    float2 sb = __half22float2(*(__half2*)&ps.y);

    float4 acc = make_float4(0.f, 0.f, 0.f, 0.f);

    int i   = g_rowptr[node];
    int end = g_rowptr[node + 1];

    while (i + 8 <= end) {
        int2  ee[8];
        uint2 pp[8];
#pragma unroll
        for (int u = 0; u < 8; ++u) ee[u] = g_edge[i + u];
#pragma unroll
        for (int u = 0; u < 8; ++u) pp[u] = hh[ee[u].x * 32 + lane];
#pragma unroll
        for (int u = 0; u < 8; ++u) {
            float w = __int_as_float(ee[u].y);
            float2 fa = __half22float2(*(__half2*)&pp[u].x);
            float2 fb = __half22float2(*(__half2*)&pp[u].y);
            acc.x = fmaf(w, fa.x, acc.x); acc.y = fmaf(w, fa.y, acc.y);
            acc.z = fmaf(w, fb.x, acc.z); acc.w = fmaf(w, fb.y, acc.w);
        }
        i += 8;
    }
    if (i + 4 <= end) {
        int2  ee[4];
        uint2 pp[4];
#pragma unroll
        for (int u = 0; u < 4; ++u) ee[u] = g_edge[i + u];
#pragma unroll
        for (int u = 0; u < 4; ++u) pp[u] = hh[ee[u].x * 32 + lane];
#pragma unroll
        for (int u = 0; u < 4; ++u) {
            float w = __int_as_float(ee[u].y);
            float2 fa = __half22float2(*(__half2*)&pp[u].x);
            float2 fb = __half22float2(*(__half2*)&pp[u].y);
            acc.x = fmaf(w, fa.x, acc.x); acc.y = fmaf(w, fa.y, acc.y);
            acc.z = fmaf(w, fb.x, acc.z); acc.w = fmaf(w, fb.y, acc.w);
        }
        i += 4;
    }
    for (; i < end; ++i) {
        int2 e = g_edge[i];
        float w = __int_as_float(e.y);
        uint2 p = hh[e.x * 32 + lane];
        float2 fa = __half22float2(*(__half2*)&p.x);
        float2 fb = __half22float2(*(__half2*)&p.y);
        acc.x = fmaf(w, fa.x, acc.x); acc.y = fmaf(w, fa.y, acc.y);
        acc.z = fmaf(w, fb.x, acc.z); acc.w = fmaf(w, fb.y, acc.w);
    }

    float di2 = di * di;
    float4 bb = ((const float4*)b)[lane];
    float4 v;
    v.x = fmaf(di, acc.x, fmaf(di2, sa.x, bb.x));
    v.y = fmaf(di, acc.y, fmaf(di2, sa.y, bb.y));
    v.z = fmaf(di, acc.z, fmaf(di2, sb.x, bb.z));
    v.w = fmaf(di, acc.w, fmaf(di2, sb.y, bb.w));

    float4 aa = ((const float4*)a)[lane];
    v.x = (v.x > 0.f) ? v.x : aa.x * v.x;
    v.y = (v.y > 0.f) ? v.y : aa.y * v.y;
    v.z = (v.z > 0.f) ? v.z : aa.z * v.z;
    v.w = (v.w > 0.f) ? v.w : aa.w * v.w;

    float4* Z = use_ext ? (float4*)Oext : (float4*)g_z;
    Z[node * 32 + lane] = v;
}

// -------- launch --------
extern "C" void kernel_launch(void* const* d_in, const int* in_sizes, int n_in,
                              void* d_out, int out_size) {
    const float* x  = (const float*)d_in[0];
    const int*   ei = (const int*)d_in[1];
    const float* ew = (const float*)d_in[2];
    const float* W1 = (const float*)d_in[3];
    const float* b1 = (const float*)d_in[4];
    const float* a1 = (const float*)d_in[5];
    const float* W2 = (const float*)d_in[6];
    const float* b2 = (const float*)d_in[7];
    const float* a2 = (const float*)d_in[8];
    float* out = (float*)d_out;

    const int N = in_sizes[0] / DD;   // 50000
    const int E = in_sizes[2];        // 800000
    const int nb = (N + 1023) / 1024; // 49

    cudaStream_t s2;
    cudaEvent_t evFork, evJoin;
    cudaStreamCreateWithFlags(&s2, cudaStreamNonBlocking);
    cudaEventCreateWithFlags(&evFork, cudaEventDisableTiming);
    cudaEventCreateWithFlags(&evJoin, cudaEventDisableTiming);

    const int gemm_tiles = (N + 127) / 128;       // 391
    const int agg_grid   = (N * 32 + 255) / 256;

    // fork: prep chain on s2
    cudaEventRecord(evFork, 0);
    cudaStreamWaitEvent(s2, evFork, 0);
    k_init      <<<(N + 255) / 256, 256, 0, s2>>>(ei, N);
    k_convert   <<<(E + 255) / 256, 256, 0, s2>>>(ei, ew, E);
    k_scan_fused<<<nb, 1024, 0, s2>>>(N);
    k_place     <<<(E + 255) / 256, 256, 0, s2>>>(ew, E);
    cudaEventRecord(evJoin, s2);

    // concurrent on default stream: W split + layer-1 GEMM (-> g_hh1)
    k_splitw<<<(DD * DD + 255) / 256, 256>>>(W1, W2);
    k_gemm<<<gemm_tiles, 256>>>(x, 0, 0, N);

    // join, then the dependent pipeline
    cudaStreamWaitEvent(0, evJoin, 0);
    k_aggregate<<<agg_grid, 256>>>(b1, a1, out, 0, 0, N);
    k_gemm<<<gemm_tiles, 256>>>(nullptr, 1, 1, N);
    k_aggregate<<<agg_grid, 256>>>(b2, a2, out, 1, 1, N);
}

// round 16
// speedup vs baseline: 1.3446x; 1.2669x over previous
#include <cuda_runtime.h>
#include <cuda_fp16.h>

#define NN 50000
#define DD 128
#define EE 800000

// Scratch (__device__ globals; no allocations allowed)
__device__ __align__(16) __half g_hh1[NN * DD]; // layer-1 h (fp16)
__device__ __align__(16) __half g_hh2[NN * DD]; // layer-2 h (fp16)
__device__ __align__(16) __half g_z16[NN * DD]; // layer-1 activation (fp16)
__device__ float  g_dinv [NN];
__device__ int    g_cnt  [NN];
__device__ int    g_rowptr[NN + 1];
__device__ int    g_cursor[NN];
__device__ int2   g_sd   [EE];
__device__ int2   g_edge [EE];                  // CSR-ordered (src, dinv[s]*ew bits)
__device__ int    g_bsum [64];
__device__ int    g_boff [64];
__device__ int    g_done;
__device__ int    g_flag;
__device__ int    g_is64;
__device__ __align__(16) __half g_w1t[DD * DD]; // W1^T fp16 [n][k]
__device__ __align__(16) __half g_w2t[DD * DD]; // W2^T fp16 [n][k]

// ---------------- init (detect + per-node init + scan flag reset) ----------------
__global__ void k_init(const int* __restrict__ ei32, int n) {
    int i = blockIdx.x * blockDim.x + threadIdx.x;
    if (i < n) {
        g_dinv[i] = 1.0f;
        g_cnt[i]  = 0;
    }
    if (blockIdx.x == 0 && threadIdx.x == 0) {
        int acc = 0;
#pragma unroll
        for (int k = 0; k < 64; ++k) acc |= ei32[2 * k + 1];
        g_is64 = (acc == 0) ? 1 : 0;
        g_done = 0;
        g_flag = 0;
    }
}

// ---------------- transpose W1/W2 to fp16 [n][k] ----------------
__global__ void k_prepw(const float* __restrict__ W1,
                        const float* __restrict__ W2) {
    int i = blockIdx.x * blockDim.x + threadIdx.x;
    if (i >= DD * DD) return;
    int k = i >> 7;      // row of W (k index)
    int n = i & 127;     // col of W (n index)
    g_w1t[n * DD + k] = __float2half(W1[i]);
    g_w2t[n * DD + k] = __float2half(W2[i]);
}

// ---- convert + degree + histogram (1 edge/thread; int64 read as int2) ----
__global__ void k_convert(const int* __restrict__ ei32,
                          const float* __restrict__ ew, int E) {
    int e = blockIdx.x * blockDim.x + threadIdx.x;
    if (e >= E) return;
    int s, d;
    if (g_is64) {
        const int2* p = (const int2*)ei32;   // int64 little-endian: .x = low word
        s = p[e].x;
        d = p[E + e].x;
    } else {
        s = ei32[e];
        d = ei32[E + e];
    }
    g_sd[e] = make_int2(s, d);
    atomicAdd(&g_dinv[d], ew[e]);
    atomicAdd(&g_cnt[d], 1);
}

// ------- fused scan: one launch, last-block pattern (+ dinv finalize) -------
__global__ void k_scan_fused(int N) {
    __shared__ int wsum[32];
    int nb   = gridDim.x;
    int b    = blockIdx.x;
    int tid  = threadIdx.x;
    int lane = tid & 31;
    int wid  = tid >> 5;
    int i = b * 1024 + tid;
    int v = (i < N) ? g_cnt[i] : 0;

    int s = v;
#pragma unroll
    for (int o = 1; o < 32; o <<= 1) {
        int t = __shfl_up_sync(0xFFFFFFFFu, s, o);
        if (lane >= o) s += t;
    }
    if (lane == 31) wsum[wid] = s;
    __syncthreads();
    if (wid == 0) {
        int ws = wsum[lane];
#pragma unroll
        for (int o = 1; o < 32; o <<= 1) {
            int t = __shfl_up_sync(0xFFFFFFFFu, ws, o);
            if (lane >= o) ws += t;
        }
        wsum[lane] = ws;
    }
    __syncthreads();

    if (tid == 0) {
        g_bsum[b] = wsum[31];
        __threadfence();
        int t = atomicAdd(&g_done, 1);
        if (t == nb - 1) {
            int run = 0;
            for (int j = 0; j < nb; ++j) {
                int bs = atomicAdd(&g_bsum[j], 0);
                g_boff[j] = run;
                run += bs;
            }
            g_rowptr[N] = run;
            __threadfence();
            atomicExch(&g_flag, 1);
        }
    }
    if (tid == 0) {
        while (atomicAdd(&g_flag, 0) == 0) __nanosleep(64);
    }
    __syncthreads();
    int excl = s - v + ((wid > 0) ? wsum[wid - 1] : 0) + g_boff[b];
    if (i < N) {
        g_rowptr[i] = excl;
        g_cursor[i] = excl;
        float deg = g_dinv[i];
        g_dinv[i] = (deg > 0.0f) ? rsqrtf(deg) : 0.0f;
    }
}

// -------- place edges (1 edge/thread; record = (src, dinv[s]*ew)) --------
__global__ void k_place(const float* __restrict__ ew, int E) {
    int e = blockIdx.x * blockDim.x + threadIdx.x;
    if (e >= E) return;
    int2 sd = g_sd[e];
    float wse = g_dinv[sd.x] * ew[e];
    int pos = atomicAdd(&g_cursor[sd.y], 1);
    g_edge[pos] = make_int2(sd.x, __float_as_int(wse));
}

// ---------------- fp16 MMA macro (m16n8k16, fp32 accum) ----------------
#define MMA_F16(d, a0, a1, a2, a3, b0, b1)                                    \
    asm volatile(                                                             \
        "mma.sync.aligned.m16n8k16.row.col.f32.f16.f16.f32 "                  \
        "{%0,%1,%2,%3}, {%4,%5,%6,%7}, {%8,%9}, {%0,%1,%2,%3};"               \
        : "+f"(d[0]), "+f"(d[1]), "+f"(d[2]), "+f"(d[3])                      \
        : "r"(a0), "r"(a1), "r"(a2), "r"(a3), "r"(b0), "r"(b1))

// ------- GEMM: hh_dst = fp16(X @ W) via fp16 tensor-core mma -------
// Block 256 = 8 warps; tile 128 rows x 128 cols; K in 8 chunks of 16.
__global__ void __launch_bounds__(256)
k_gemm(const float* __restrict__ Xext, int use_gz, int dst2, int N) {
    __shared__ __half xs[128][24];   // [row][k] fp16, pad to 24 (48B rows)
    __shared__ __half ws[128][24];   // [n][k]  fp16

    const __half* __restrict__ Wt = use_gz ? g_w2t : g_w1t;
    __half* __restrict__ H = dst2 ? g_hh2 : g_hh1;

    int tid  = threadIdx.x;
    int lane = tid & 31;
    int warp = tid >> 5;
    int grp  = lane >> 2;   // 0..7
    int tig  = lane & 3;    // 0..3
    int wm   = warp & 3;    // 32-row tile
    int wn   = warp >> 2;   // 64-col half
    int r0   = blockIdx.x * 128;

    float acc[2][8][4];
#pragma unroll
    for (int mt = 0; mt < 2; ++mt)
#pragma unroll
        for (int nt = 0; nt < 8; ++nt)
#pragma unroll
            for (int c = 0; c < 4; ++c) acc[mt][nt][c] = 0.0f;

    for (int chunk = 0; chunk < 8; ++chunk) {
        int k0 = chunk * 16;
        // load X tile: 128 rows x 16 k; each thread 8 halfs
        {
            int row  = tid >> 1;
            int part = (tid & 1) * 8;
            if (use_gz) {
                uint4 v = make_uint4(0u, 0u, 0u, 0u);
                if (r0 + row < N)
                    v = *(const uint4*)&g_z16[(r0 + row) * DD + k0 + part];
                *(uint4*)&xs[row][part] = v;
            } else {
                float4 v0 = make_float4(0.f, 0.f, 0.f, 0.f), v1 = v0;
                if (r0 + row < N) {
                    v0 = *(const float4*)&Xext[(r0 + row) * DD + k0 + part];
                    v1 = *(const float4*)&Xext[(r0 + row) * DD + k0 + part + 4];
                }
                __half2* dst = (__half2*)&xs[row][part];
                dst[0] = __floats2half2_rn(v0.x, v0.y);
                dst[1] = __floats2half2_rn(v0.z, v0.w);
                dst[2] = __floats2half2_rn(v1.x, v1.y);
                dst[3] = __floats2half2_rn(v1.z, v1.w);
            }
            // W tile: [n][k] straight copy
            *(uint4*)&ws[row][part] = *(const uint4*)&Wt[row * DD + k0 + part];
        }
        __syncthreads();

        unsigned a[2][4];
#pragma unroll
        for (int mt = 0; mt < 2; ++mt) {
            int ar = wm * 32 + mt * 16 + grp;
            a[mt][0] = *(const unsigned*)&xs[ar    ][2 * tig    ];
            a[mt][1] = *(const unsigned*)&xs[ar + 8][2 * tig    ];
            a[mt][2] = *(const unsigned*)&xs[ar    ][2 * tig + 8];
            a[mt][3] = *(const unsigned*)&xs[ar + 8][2 * tig + 8];
        }
#pragma unroll
        for (int nt = 0; nt < 8; ++nt) {
            int n = wn * 64 + nt * 8 + grp;
            unsigned b0 = *(const unsigned*)&ws[n][2 * tig    ];
            unsigned b1 = *(const unsigned*)&ws[n][2 * tig + 8];
            MMA_F16(acc[0][nt], a[0][0], a[0][1], a[0][2], a[0][3], b0, b1);
            MMA_F16(acc[1][nt], a[1][0], a[1][1], a[1][2], a[1][3], b0, b1);
        }
        __syncthreads();
    }

#pragma unroll
    for (int mt = 0; mt < 2; ++mt) {
#pragma unroll
        for (int nt = 0; nt < 8; ++nt) {
            int row = r0 + wm * 32 + mt * 16 + grp;
            int col = wn * 64 + nt * 8 + 2 * tig;
            if (row < N)
                *(__half2*)&H[row * DD + col] =
                    __floats2half2_rn(acc[mt][nt][0], acc[mt][nt][1]);
            if (row + 8 < N)
                *(__half2*)&H[(row + 8) * DD + col] =
                    __floats2half2_rn(acc[mt][nt][2], acc[mt][nt][3]);
        }
    }
}

// -------- fused aggregate: out = dinv[d]*Σ wse*h[s] + dinv[d]^2*h[d] + b; PReLU --------
// use_ext=0 -> write z fp16 (g_z16); use_ext=1 -> write fp32 Oext
__global__ void k_aggregate(const float* __restrict__ b,
                            const float* __restrict__ a,
                            float* __restrict__ Oext, int use_ext, int src2, int N) {
    int node = (blockIdx.x * blockDim.x + threadIdx.x) >> 5;
    if (node >= N) return;
    int lane = threadIdx.x & 31;

    const uint2* __restrict__ hh = src2 ? (const uint2*)g_hh2 : (const uint2*)g_hh1;
    float di = g_dinv[node];

    uint2 ps = hh[node * 32 + lane];   // self row
    float2 sa = __half22float2(*(__half2*)&ps.x);
    float2 sb = __half22float2(*(__half2*)&ps.y);

    float4 acc = make_float4(0.f, 0.f, 0.f, 0.f);

    int i   = g_rowptr[node];
    int end = g_rowptr[node + 1];

    while (i + 8 <= end) {
        int2  ee[8];
        uint2 pp[8];
#pragma unroll
        for (int u = 0; u < 8; ++u) ee[u] = g_edge[i + u];
#pragma unroll
        for (int u = 0; u < 8; ++u) pp[u] = hh[ee[u].x * 32 + lane];
#pragma unroll
        for (int u = 0; u < 8; ++u) {
            float w = __int_as_float(ee[u].y);
            float2 fa = __half22float2(*(__half2*)&pp[u].x);
            float2 fb = __half22float2(*(__half2*)&pp[u].y);
            acc.x = fmaf(w, fa.x, acc.x); acc.y = fmaf(w, fa.y, acc.y);
            acc.z = fmaf(w, fb.x, acc.z); acc.w = fmaf(w, fb.y, acc.w);
        }
        i += 8;
    }
    if (i + 4 <= end) {
        int2  ee[4];
        uint2 pp[4];
#pragma unroll
        for (int u = 0; u < 4; ++u) ee[u] = g_edge[i + u];
#pragma unroll
        for (int u = 0; u < 4; ++u) pp[u] = hh[ee[u].x * 32 + lane];
#pragma unroll
        for (int u = 0; u < 4; ++u) {
            float w = __int_as_float(ee[u].y);
            float2 fa = __half22float2(*(__half2*)&pp[u].x);
            float2 fb = __half22float2(*(__half2*)&pp[u].y);
            acc.x = fmaf(w, fa.x, acc.x); acc.y = fmaf(w, fa.y, acc.y);
            acc.z = fmaf(w, fb.x, acc.z); acc.w = fmaf(w, fb.y, acc.w);
        }
        i += 4;
    }
    for (; i < end; ++i) {
        int2 e = g_edge[i];
        float w = __int_as_float(e.y);
        uint2 p = hh[e.x * 32 + lane];
        float2 fa = __half22float2(*(__half2*)&p.x);
        float2 fb = __half22float2(*(__half2*)&p.y);
        acc.x = fmaf(w, fa.x, acc.x); acc.y = fmaf(w, fa.y, acc.y);
        acc.z = fmaf(w, fb.x, acc.z); acc.w = fmaf(w, fb.y, acc.w);
    }

    float di2 = di * di;
    float4 bb = ((const float4*)b)[lane];
    float4 v;
    v.x = fmaf(di, acc.x, fmaf(di2, sa.x, bb.x));
    v.y = fmaf(di, acc.y, fmaf(di2, sa.y, bb.y));
    v.z = fmaf(di, acc.z, fmaf(di2, sb.x, bb.z));
    v.w = fmaf(di, acc.w, fmaf(di2, sb.y, bb.w));

    float4 aa = ((const float4*)a)[lane];
    v.x = (v.x > 0.f) ? v.x : aa.x * v.x;
    v.y = (v.y > 0.f) ? v.y : aa.y * v.y;
    v.z = (v.z > 0.f) ? v.z : aa.z * v.z;
    v.w = (v.w > 0.f) ? v.w : aa.w * v.w;

    if (use_ext) {
        ((float4*)Oext)[node * 32 + lane] = v;
    } else {
        uint2 pz;
        *(__half2*)&pz.x = __floats2half2_rn(v.x, v.y);
        *(__half2*)&pz.y = __floats2half2_rn(v.z, v.w);
        ((uint2*)g_z16)[node * 32 + lane] = pz;
    }
}

// -------- launch --------
extern "C" void kernel_launch(void* const* d_in, const int* in_sizes, int n_in,
                              void* d_out, int out_size) {
    const float* x  = (const float*)d_in[0];
    const int*   ei = (const int*)d_in[1];
    const float* ew = (const float*)d_in[2];
    const float* W1 = (const float*)d_in[3];
    const float* b1 = (const float*)d_in[4];
    const float* a1 = (const float*)d_in[5];
    const float* W2 = (const float*)d_in[6];
    const float* b2 = (const float*)d_in[7];
    const float* a2 = (const float*)d_in[8];
    float* out = (float*)d_out;

    const int N = in_sizes[0] / DD;   // 50000
    const int E = in_sizes[2];        // 800000
    const int nb = (N + 1023) / 1024; // 49

    cudaStream_t s2;
    cudaEvent_t evFork, evJoin;
    cudaStreamCreateWithFlags(&s2, cudaStreamNonBlocking);
    cudaEventCreateWithFlags(&evFork, cudaEventDisableTiming);
    cudaEventCreateWithFlags(&evJoin, cudaEventDisableTiming);

    const int gemm_tiles = (N + 127) / 128;       // 391
    const int agg_grid   = (N * 32 + 255) / 256;

    // fork: prep chain on s2
    cudaEventRecord(evFork, 0);
    cudaStreamWaitEvent(s2, evFork, 0);
    k_init      <<<(N + 255) / 256, 256, 0, s2>>>(ei, N);
    k_convert   <<<(E + 255) / 256, 256, 0, s2>>>(ei, ew, E);
    k_scan_fused<<<nb, 1024, 0, s2>>>(N);
    k_place     <<<(E + 255) / 256, 256, 0, s2>>>(ew, E);
    cudaEventRecord(evJoin, s2);

    // concurrent on default stream: W prep + layer-1 GEMM (-> g_hh1)
    k_prepw<<<(DD * DD + 255) / 256, 256>>>(W1, W2);
    k_gemm<<<gemm_tiles, 256>>>(x, 0, 0, N);

    // join, then the dependent pipeline
    cudaStreamWaitEvent(0, evJoin, 0);
    k_aggregate<<<agg_grid, 256>>>(b1, a1, out, 0, 0, N);
    k_gemm<<<gemm_tiles, 256>>>(nullptr, 1, 1, N);
    k_aggregate<<<agg_grid, 256>>>(b2, a2, out, 1, 1, N);
}